// round 6
// baseline (speedup 1.0000x reference)
#include <cuda_runtime.h>
#include <math.h>
#include <stdint.h>

#define Bsz 32
#define Ssz 2048
#define Isz 256
#define Hsz 256
#define Msz 1024   // 4*H, packed as m = j*4 + g  (g: 0=f,1=i,2=c,3=o)

typedef unsigned long long ull;

// ------------------------------- f32x2 helpers ---------------------------------
__device__ __forceinline__ ull pack2(float lo, float hi) {
    ull r; asm("mov.b64 %0, {%1,%2};" : "=l"(r) : "f"(lo), "f"(hi)); return r;
}
__device__ __forceinline__ void unpack2(float& lo, float& hi, ull v) {
    asm("mov.b64 {%0,%1}, %2;" : "=f"(lo), "=f"(hi) : "l"(v));
}
__device__ __forceinline__ void fma2(ull& d, ull a, ull b) {
    asm("fma.rn.f32x2 %0, %1, %2, %0;" : "+l"(d) : "l"(a), "l"(b));
}
__device__ __forceinline__ ull add2(ull a, ull b) {
    ull r; asm("add.rn.f32x2 %0, %1, %2;" : "=l"(r) : "l"(a), "l"(b)); return r;
}

// ------------------------------- device scratch -------------------------------
__device__ float g_Wx[Isz * Msz];                      // [k][m], x-part rows of W
__device__ float g_Wh[Hsz * Msz];                      // [k][m], h-part rows of W
__device__ float g_bias[Msz];
__device__ float g_xp[(size_t)Bsz * Ssz * Msz];        // [t][b][m]  (256 MB)

// ------------------------------- pack ------------------------------------------
__global__ void pack_kernel(const float* __restrict__ Wf, const float* __restrict__ Wi,
                            const float* __restrict__ Wc, const float* __restrict__ Wo,
                            const float* __restrict__ bf, const float* __restrict__ bi,
                            const float* __restrict__ bc, const float* __restrict__ bo) {
    int idx = blockIdx.x * blockDim.x + threadIdx.x;   // over (k in 0..511, j in 0..255)
    if (idx < 512 * 256) {
        int k = idx >> 8;      // row of W_all (0..511): [0,256) = h-part, [256,512) = x-part
        int j = idx & 255;
        const float* W[4] = {Wf, Wi, Wc, Wo};
        #pragma unroll
        for (int g = 0; g < 4; g++) {
            float v = W[g][k * Hsz + j];
            int m = j * 4 + g;
            if (k < Hsz) g_Wh[k * Msz + m] = v;
            else         g_Wx[(k - Hsz) * Msz + m] = v;
        }
        if (k == 0) {
            const float* bias[4] = {bf, bi, bc, bo};
            #pragma unroll
            for (int g = 0; g < 4; g++) g_bias[j * 4 + g] = bias[g][j];
        }
    }
}

// ------------------------------- xproj GEMM (f32x2) ----------------------------
// xp[r][m] = sum_k x_row(r)[k] * Wx[k][m] + bias[m],  r = t*32 + b
#define XBM 128
#define XBN 128
#define XBK 8

__global__ __launch_bounds__(256) void xproj_kernel(const float* __restrict__ x) {
    __shared__ float As[XBK][XBM + 4];
    __shared__ float Bs[XBK][XBN];

    int bn = blockIdx.x;               // 0..7    (m blocks)
    int bm = blockIdx.y;               // 0..511  (row blocks)
    int tid = threadIdx.x;
    int tx = tid & 15;                 // col group
    int ty = tid >> 4;                 // row group

    int r0 = bm * XBM;
    int m0 = bn * XBN;

    int arow = tid >> 1, akq = tid & 1;
    int r = r0 + arow;
    int b = r & 31, t = r >> 5;
    const float* arow_ptr = x + ((size_t)b * Ssz + t) * Isz;

    int bk = tid >> 5, bmq = tid & 31;
    const float* brow_ptr = g_Wx + (size_t)bk * Msz + m0 + bmq * 4;

    ull acc2[8][4];
    #pragma unroll
    for (int i = 0; i < 8; i++)
        #pragma unroll
        for (int jp = 0; jp < 4; jp++) acc2[i][jp] = 0ull;

    for (int k0 = 0; k0 < Isz; k0 += XBK) {
        float4 av = *(const float4*)(arow_ptr + k0 + akq * 4);
        As[akq * 4 + 0][arow] = av.x;
        As[akq * 4 + 1][arow] = av.y;
        As[akq * 4 + 2][arow] = av.z;
        As[akq * 4 + 3][arow] = av.w;
        *(float4*)&Bs[bk][bmq * 4] = *(const float4*)(brow_ptr + (size_t)k0 * Msz);
        __syncthreads();
        #pragma unroll
        for (int kk = 0; kk < XBK; kk++) {
            float4 aA = *(float4*)&As[kk][ty * 8];
            float4 aB = *(float4*)&As[kk][ty * 8 + 4];
            ulonglong2 bL = *(ulonglong2*)&Bs[kk][tx * 8];
            ulonglong2 bH = *(ulonglong2*)&Bs[kk][tx * 8 + 4];
            ull b2[4] = {bL.x, bL.y, bH.x, bH.y};
            float ar[8] = {aA.x, aA.y, aA.z, aA.w, aB.x, aB.y, aB.z, aB.w};
            #pragma unroll
            for (int i = 0; i < 8; i++) {
                ull a2 = pack2(ar[i], ar[i]);
                #pragma unroll
                for (int jp = 0; jp < 4; jp++) fma2(acc2[i][jp], a2, b2[jp]);
            }
        }
        __syncthreads();
    }

    ull bias2[4];
    {
        ulonglong2 bL = *(const ulonglong2*)(g_bias + m0 + tx * 8);
        ulonglong2 bH = *(const ulonglong2*)(g_bias + m0 + tx * 8 + 4);
        bias2[0] = bL.x; bias2[1] = bL.y; bias2[2] = bH.x; bias2[3] = bH.y;
    }
    #pragma unroll
    for (int i = 0; i < 8; i++) {
        int rr = r0 + ty * 8 + i;
        float* dst = g_xp + (size_t)rr * Msz + m0 + tx * 8;
        ulonglong2 oL, oH;
        oL.x = add2(acc2[i][0], bias2[0]);
        oL.y = add2(acc2[i][1], bias2[1]);
        oH.x = add2(acc2[i][2], bias2[2]);
        oH.y = add2(acc2[i][3], bias2[3]);
        *(ulonglong2*)dst = oL;
        *(ulonglong2*)(dst + 4) = oH;
    }
}

// ------------------------------- clustered recurrence --------------------------
// 16 clusters x 8 CTAs x 512 threads. Cluster c owns batches {2c, 2c+1}.
// CTA rank r owns j in [32r, 32r+32). Warp w owns j-pair {2w, 2w+1} (local) for
// both batches; lane l owns k-slice [8l, 8l+8). Weights in registers (k-pair
// packed f32x2). 16-value butterfly; h broadcast via DSMEM stores to all 8
// peers + cluster barrier. h never touches gmem. NO remote stores at the last
// step, and a trailing cluster sync before exit (DSMEM lifetime safety).
__global__ __launch_bounds__(512, 1) __cluster_dims__(8, 1, 1)
void lstm_rec(const float* __restrict__ h0, const float* __restrict__ c0,
              float* __restrict__ out, int write_finals) {
    __shared__ __align__(16) float h_s[2][2 * Hsz];   // [buf][b_local*256 + j]

    unsigned rank;
    asm("mov.u32 %0, %%cluster_ctarank;" : "=r"(rank));
    int clu = blockIdx.x >> 3;
    int tid = threadIdx.x;
    int w = tid >> 5;
    int lane = tid & 31;

    unsigned my_hs = (unsigned)__cvta_generic_to_shared(h_s);

    int jg0 = (int)rank * 32 + w * 2;   // first of this warp's two global j's

    // weights: w2[kp][jj*4+g] = {Wh[8l+2kp][4(jg0+jj)+g], Wh[8l+2kp+1][...]}
    ull w2[4][8];
    #pragma unroll
    for (int kp = 0; kp < 4; kp++) {
        const float* re = g_Wh + (size_t)(8 * lane + 2 * kp) * Msz;
        const float* ro = re + Msz;
        float4 e0 = *(const float4*)(re + 4 * jg0);
        float4 o0 = *(const float4*)(ro + 4 * jg0);
        float4 e1 = *(const float4*)(re + 4 * (jg0 + 1));
        float4 o1 = *(const float4*)(ro + 4 * (jg0 + 1));
        w2[kp][0] = pack2(e0.x, o0.x); w2[kp][1] = pack2(e0.y, o0.y);
        w2[kp][2] = pack2(e0.z, o0.z); w2[kp][3] = pack2(e0.w, o0.w);
        w2[kp][4] = pack2(e1.x, o1.x); w2[kp][5] = pack2(e1.y, o1.y);
        w2[kp][6] = pack2(e1.z, o1.z); w2[kp][7] = pack2(e1.w, o1.w);
    }

    // this lane's value id: v = lane>>1 = b*8 + jj*4 + g
    int v_me = lane >> 1;
    int b_me = v_me >> 3;
    int o_me = v_me & 7;
    int jj_me = o_me >> 2, g_me = o_me & 3;
    int jg_me = jg0 + jj_me;
    int bg_me = clu * 2 + b_me;
    bool owner = ((lane & 7) == 0);     // holds g==0 value of a (b, j)

    // init h0 into buf 0 (own CTA copy: full 2 batches x 256 j)
    {
        int b = tid >> 8, j = tid & 255;
        h_s[0][b * Hsz + j] = h0[(clu * 2 + b) * Hsz + j];
    }
    float c_val = owner ? c0[bg_me * Hsz + jg_me] : 0.f;

    float xv = g_xp[(size_t)bg_me * Msz + jg_me * 4 + g_me];   // t=0

    // hoisted output pointers (owner lanes only use them)
    float* out_hj = out + (size_t)bg_me * Ssz * Hsz + jg_me;            // + t*Hsz per step
    const float* xp_bj = g_xp + (size_t)bg_me * Msz + jg_me * 4 + g_me; // + t*Bsz*Msz
    const size_t fin_off = (size_t)Bsz * Ssz * Hsz;

    __syncthreads();   // h_s init visible CTA-locally before anyone reads it
    asm volatile("barrier.cluster.arrive.aligned;" ::: "memory");
    asm volatile("barrier.cluster.wait.aligned;" ::: "memory");

    for (int t = 0; t < Ssz; t++) {
        const float* hb = &h_s[t & 1][0];

        // batch 0 pass
        ulonglong2 hA0 = *(const ulonglong2*)(hb + 8 * lane);
        ulonglong2 hB0 = *(const ulonglong2*)(hb + 8 * lane + 4);
        ull h20[4] = {hA0.x, hA0.y, hB0.x, hB0.y};
        ull acc2[8];
        #pragma unroll
        for (int o = 0; o < 8; o++) acc2[o] = 0ull;
        #pragma unroll
        for (int kp = 0; kp < 4; kp++)
            #pragma unroll
            for (int o = 0; o < 8; o++) fma2(acc2[o], w2[kp][o], h20[kp]);

        float acc[16];
        #pragma unroll
        for (int o = 0; o < 8; o++) {
            float lo, hi; unpack2(lo, hi, acc2[o]); acc[o] = lo + hi;
        }

        // batch 1 pass (reuse acc2)
        ulonglong2 hA1 = *(const ulonglong2*)(hb + Hsz + 8 * lane);
        ulonglong2 hB1 = *(const ulonglong2*)(hb + Hsz + 8 * lane + 4);
        ull h21[4] = {hA1.x, hA1.y, hB1.x, hB1.y};
        #pragma unroll
        for (int o = 0; o < 8; o++) acc2[o] = 0ull;
        #pragma unroll
        for (int kp = 0; kp < 4; kp++)
            #pragma unroll
            for (int o = 0; o < 8; o++) fma2(acc2[o], w2[kp][o], h21[kp]);
        #pragma unroll
        for (int o = 0; o < 8; o++) {
            float lo, hi; unpack2(lo, hi, acc2[o]); acc[8 + o] = lo + hi;
        }

        // butterfly: 16 values over 32 lanes; lane L ends with value (L>>1)
        int cnt = 16;
        #pragma unroll
        for (int off = 16; off >= 2; off >>= 1) {
            cnt >>= 1;
            bool upper = (lane & off) != 0;
            #pragma unroll
            for (int v = 0; v < cnt; v++) {
                float send = upper ? acc[v] : acc[v + cnt];
                float recv = __shfl_xor_sync(0xffffffffu, send, off);
                acc[v] = (upper ? acc[v + cnt] : acc[v]) + recv;
            }
        }
        acc[0] += __shfl_xor_sync(0xffffffffu, acc[0], 1);

        float pre = acc[0] + xv;
        float a;
        if (g_me == 2) { float e = __expf(-2.f * pre); a = __fdividef(2.f, 1.f + e) - 1.f; }
        else           { a = __fdividef(1.f, 1.f + __expf(-pre)); }

        int base = lane & ~7;
        float fg = __shfl_sync(0xffffffffu, a, base);
        float ig = __shfl_sync(0xffffffffu, a, base + 2);
        float cg = __shfl_sync(0xffffffffu, a, base + 4);
        float og = __shfl_sync(0xffffffffu, a, base + 6);

        bool not_last = (t + 1 < Ssz);
        float hn = 0.f;
        int nb = (t + 1) & 1;
        if (owner) {
            c_val = c_val * fg + ig * cg;
            float e = __expf(-2.f * c_val);
            hn = og * (__fdividef(2.f, 1.f + e) - 1.f);
            // broadcast hn into all 8 cluster CTAs' h_s[nb] — ONLY if a next
            // step exists (remote stores at the last step would race CTA exit)
            if (not_last) {
                unsigned off4 = (unsigned)(nb * (2 * Hsz) + b_me * Hsz + jg_me) * 4u;
                #pragma unroll
                for (int r = 0; r < 8; r++) {
                    unsigned raddr;
                    asm("mapa.shared::cluster.u32 %0, %1, %2;" : "=r"(raddr) : "r"(my_hs + off4), "r"(r));
                    asm volatile("st.shared::cluster.f32 [%0], %1;" :: "r"(raddr), "f"(hn) : "memory");
                }
            }
        }

        if (not_last)
            asm volatile("barrier.cluster.arrive.aligned;" ::: "memory");

        // DRAM work overlapped with peers' arrival
        if (owner) {
            out_hj[(size_t)t * Hsz] = hn;
            if (!not_last && write_finals) {
                out[fin_off + (size_t)bg_me * Hsz + jg_me] = hn;                          // h_f
                out[fin_off + (size_t)Bsz * Hsz + (size_t)bg_me * Hsz + jg_me] = c_val;   // c_f
            }
        }
        if (not_last) {
            xv = __ldg(xp_bj + (size_t)(t + 1) * Bsz * Msz);
            asm volatile("barrier.cluster.wait.aligned;" ::: "memory");
        }
    }

    // lifetime safety: no CTA exits while any cluster peer could have DSMEM
    // ops in flight toward it
    asm volatile("barrier.cluster.arrive.aligned;" ::: "memory");
    asm volatile("barrier.cluster.wait.aligned;" ::: "memory");
}

// ------------------------------- launch ----------------------------------------
extern "C" void kernel_launch(void* const* d_in, const int* in_sizes, int n_in,
                              void* d_out, int out_size) {
    const float* x  = (const float*)d_in[0];
    const float* h0 = (const float*)d_in[1];
    const float* c0 = (const float*)d_in[2];
    const float* Wf = (const float*)d_in[3];
    const float* bf = (const float*)d_in[4];
    const float* Wi = (const float*)d_in[5];
    const float* bi = (const float*)d_in[6];
    const float* Wc = (const float*)d_in[7];
    const float* bc = (const float*)d_in[8];
    const float* Wo = (const float*)d_in[9];
    const float* bo = (const float*)d_in[10];
    float* out = (float*)d_out;

    int full = Bsz * Ssz * Hsz + 2 * Bsz * Hsz;
    int write_finals = (out_size >= full) ? 1 : 0;

    pack_kernel<<<512, 256>>>(Wf, Wi, Wc, Wo, bf, bi, bc, bo);

    dim3 grid_x(8, 512);
    xproj_kernel<<<grid_x, 256>>>(x);

    lstm_rec<<<128, 512>>>(h0, c0, out, write_finals);
}

// round 7
// speedup vs baseline: 1.0670x; 1.0670x over previous
#include <cuda_runtime.h>
#include <math.h>
#include <stdint.h>

#define Bsz 32
#define Ssz 2048
#define Isz 256
#define Hsz 256
#define Msz 1024   // 4*H, packed as m = j*4 + g  (g: 0=f,1=i,2=c,3=o)

typedef unsigned long long ull;

// ------------------------------- f32x2 helpers ---------------------------------
__device__ __forceinline__ ull pack2(float lo, float hi) {
    ull r; asm("mov.b64 %0, {%1,%2};" : "=l"(r) : "f"(lo), "f"(hi)); return r;
}
__device__ __forceinline__ void unpack2(float& lo, float& hi, ull v) {
    asm("mov.b64 {%0,%1}, %2;" : "=f"(lo), "=f"(hi) : "l"(v));
}
__device__ __forceinline__ void fma2(ull& d, ull a, ull b) {
    asm("fma.rn.f32x2 %0, %1, %2, %0;" : "+l"(d) : "l"(a), "l"(b));
}
__device__ __forceinline__ ull add2(ull a, ull b) {
    ull r; asm("add.rn.f32x2 %0, %1, %2;" : "=l"(r) : "l"(a), "l"(b)); return r;
}

// ------------------------------- mbarrier helpers ------------------------------
__device__ __forceinline__ void mbar_init(unsigned addr, unsigned count) {
    asm volatile("mbarrier.init.shared.b64 [%0], %1;" :: "r"(addr), "r"(count) : "memory");
}
__device__ __forceinline__ void mbar_expect_tx(unsigned addr, unsigned bytes) {
    asm volatile("mbarrier.arrive.expect_tx.shared.b64 _, [%0], %1;"
                 :: "r"(addr), "r"(bytes) : "memory");
}
__device__ __forceinline__ void mbar_wait(unsigned addr, unsigned parity) {
    unsigned done;
    asm volatile(
        "{\n\t.reg .pred p;\n\t"
        "mbarrier.try_wait.parity.acquire.cta.shared::cta.b64 p, [%1], %2;\n\t"
        "selp.b32 %0, 1, 0, p;\n\t}"
        : "=r"(done) : "r"(addr), "r"(parity) : "memory");
    if (!done) {
        asm volatile(
            "{\n\t.reg .pred P1;\n\t"
            "WL_%=:\n\t"
            "mbarrier.try_wait.parity.acquire.cta.shared::cta.b64 P1, [%0], %1, 0x989680;\n\t"
            "@P1 bra.uni WD_%=;\n\t"
            "bra.uni WL_%=;\n\t"
            "WD_%=:\n\t}"
            :: "r"(addr), "r"(parity) : "memory");
    }
}

// ------------------------------- device scratch -------------------------------
__device__ float g_Wx[Isz * Msz];                      // [k][m], x-part rows of W
__device__ float g_Wh[Hsz * Msz];                      // [k][m], h-part rows of W
__device__ float g_bias[Msz];
__device__ float g_xp[(size_t)Bsz * Ssz * Msz];        // [t][b][m]  (256 MB)

// ------------------------------- pack ------------------------------------------
__global__ void pack_kernel(const float* __restrict__ Wf, const float* __restrict__ Wi,
                            const float* __restrict__ Wc, const float* __restrict__ Wo,
                            const float* __restrict__ bf, const float* __restrict__ bi,
                            const float* __restrict__ bc, const float* __restrict__ bo) {
    int idx = blockIdx.x * blockDim.x + threadIdx.x;   // over (k in 0..511, j in 0..255)
    if (idx < 512 * 256) {
        int k = idx >> 8;      // row of W_all (0..511): [0,256) = h-part, [256,512) = x-part
        int j = idx & 255;
        const float* W[4] = {Wf, Wi, Wc, Wo};
        #pragma unroll
        for (int g = 0; g < 4; g++) {
            float v = W[g][k * Hsz + j];
            int m = j * 4 + g;
            if (k < Hsz) g_Wh[k * Msz + m] = v;
            else         g_Wx[(k - Hsz) * Msz + m] = v;
        }
        if (k == 0) {
            const float* bias[4] = {bf, bi, bc, bo};
            #pragma unroll
            for (int g = 0; g < 4; g++) g_bias[j * 4 + g] = bias[g][j];
        }
    }
}

// ------------------------------- xproj GEMM (f32x2) ----------------------------
#define XBM 128
#define XBN 128
#define XBK 8

__global__ __launch_bounds__(256) void xproj_kernel(const float* __restrict__ x) {
    __shared__ float As[XBK][XBM + 4];
    __shared__ float Bs[XBK][XBN];

    int bn = blockIdx.x;               // 0..7    (m blocks)
    int bm = blockIdx.y;               // 0..511  (row blocks)
    int tid = threadIdx.x;
    int tx = tid & 15;
    int ty = tid >> 4;

    int r0 = bm * XBM;
    int m0 = bn * XBN;

    int arow = tid >> 1, akq = tid & 1;
    int r = r0 + arow;
    int b = r & 31, t = r >> 5;
    const float* arow_ptr = x + ((size_t)b * Ssz + t) * Isz;

    int bk = tid >> 5, bmq = tid & 31;
    const float* brow_ptr = g_Wx + (size_t)bk * Msz + m0 + bmq * 4;

    ull acc2[8][4];
    #pragma unroll
    for (int i = 0; i < 8; i++)
        #pragma unroll
        for (int jp = 0; jp < 4; jp++) acc2[i][jp] = 0ull;

    for (int k0 = 0; k0 < Isz; k0 += XBK) {
        float4 av = *(const float4*)(arow_ptr + k0 + akq * 4);
        As[akq * 4 + 0][arow] = av.x;
        As[akq * 4 + 1][arow] = av.y;
        As[akq * 4 + 2][arow] = av.z;
        As[akq * 4 + 3][arow] = av.w;
        *(float4*)&Bs[bk][bmq * 4] = *(const float4*)(brow_ptr + (size_t)k0 * Msz);
        __syncthreads();
        #pragma unroll
        for (int kk = 0; kk < XBK; kk++) {
            float4 aA = *(float4*)&As[kk][ty * 8];
            float4 aB = *(float4*)&As[kk][ty * 8 + 4];
            ulonglong2 bL = *(ulonglong2*)&Bs[kk][tx * 8];
            ulonglong2 bH = *(ulonglong2*)&Bs[kk][tx * 8 + 4];
            ull b2[4] = {bL.x, bL.y, bH.x, bH.y};
            float ar[8] = {aA.x, aA.y, aA.z, aA.w, aB.x, aB.y, aB.z, aB.w};
            #pragma unroll
            for (int i = 0; i < 8; i++) {
                ull a2 = pack2(ar[i], ar[i]);
                #pragma unroll
                for (int jp = 0; jp < 4; jp++) fma2(acc2[i][jp], a2, b2[jp]);
            }
        }
        __syncthreads();
    }

    ull bias2[4];
    {
        ulonglong2 bL = *(const ulonglong2*)(g_bias + m0 + tx * 8);
        ulonglong2 bH = *(const ulonglong2*)(g_bias + m0 + tx * 8 + 4);
        bias2[0] = bL.x; bias2[1] = bL.y; bias2[2] = bH.x; bias2[3] = bH.y;
    }
    #pragma unroll
    for (int i = 0; i < 8; i++) {
        int rr = r0 + ty * 8 + i;
        float* dst = g_xp + (size_t)rr * Msz + m0 + tx * 8;
        ulonglong2 oL, oH;
        oL.x = add2(acc2[i][0], bias2[0]);
        oL.y = add2(acc2[i][1], bias2[1]);
        oH.x = add2(acc2[i][2], bias2[2]);
        oH.y = add2(acc2[i][3], bias2[3]);
        *(ulonglong2*)dst = oL;
        *(ulonglong2*)(dst + 4) = oH;
    }
}

// ------------------------------- clustered recurrence --------------------------
// 16 clusters x 8 CTAs x 512 threads. Cluster c owns batches {2c, 2c+1}.
// CTA rank r owns j in [32r, 32r+32). Weights register-resident (k-pair f32x2).
// Sync: DSMEM mbarriers. full[p] (count 1 + expect_tx 2048B) flips when all 512
// h words for buf p have landed via st.async; empty[p] (count 8) = all peers
// done reading buf p. No barrier.cluster in the loop (no CCTL.IVALL, no 490cyc
// UCGABAR_WAIT) — waits are mbarrier TRYWAIT (~60-90 cyc).
__global__ __launch_bounds__(512, 1) __cluster_dims__(8, 1, 1)
void lstm_rec(const float* __restrict__ h0, const float* __restrict__ c0,
              float* __restrict__ out, int write_finals) {
    __shared__ __align__(16) float h_s[2][2 * Hsz];     // [buf][b_local*256 + j]
    __shared__ __align__(8) ull mbar[4];                // full0 full1 empty0 empty1
    __shared__ unsigned s_rh[8], s_rmb[8];              // remote bases per rank

    int tid = threadIdx.x;
    int clu = blockIdx.x >> 3;
    int w = tid >> 5;
    int lane = tid & 31;
    unsigned rank;
    asm("mov.u32 %0, %%cluster_ctarank;" : "=r"(rank));

    unsigned my_hs = (unsigned)__cvta_generic_to_shared(h_s);
    unsigned my_mb = (unsigned)__cvta_generic_to_shared(mbar);

    if (tid == 0) {
        mbar_init(my_mb + 0, 1);    // full[0]
        mbar_init(my_mb + 8, 1);    // full[1]
        mbar_init(my_mb + 16, 8);   // empty[0]
        mbar_init(my_mb + 24, 8);   // empty[1]
        mbar_expect_tx(my_mb + 8, 2048);   // pre-arm full[1] for step-0 stores
    }
    if (tid < 8) {
        unsigned a;
        asm("mapa.shared::cluster.u32 %0, %1, %2;" : "=r"(a) : "r"(my_hs), "r"(tid));
        s_rh[tid] = a;
        asm("mapa.shared::cluster.u32 %0, %1, %2;" : "=r"(a) : "r"(my_mb), "r"(tid));
        s_rmb[tid] = a;            // +cur*8 = full[cur], +16+cur*8 = empty[cur]
    }

    int jg0 = (int)rank * 32 + w * 2;   // first of this warp's two global j's

    // weights: w2[kp][jj*4+g] = {Wh[8l+2kp][4(jg0+jj)+g], Wh[8l+2kp+1][...]}
    ull w2[4][8];
    #pragma unroll
    for (int kp = 0; kp < 4; kp++) {
        const float* re = g_Wh + (size_t)(8 * lane + 2 * kp) * Msz;
        const float* ro = re + Msz;
        float4 e0 = *(const float4*)(re + 4 * jg0);
        float4 o0 = *(const float4*)(ro + 4 * jg0);
        float4 e1 = *(const float4*)(re + 4 * (jg0 + 1));
        float4 o1 = *(const float4*)(ro + 4 * (jg0 + 1));
        w2[kp][0] = pack2(e0.x, o0.x); w2[kp][1] = pack2(e0.y, o0.y);
        w2[kp][2] = pack2(e0.z, o0.z); w2[kp][3] = pack2(e0.w, o0.w);
        w2[kp][4] = pack2(e1.x, o1.x); w2[kp][5] = pack2(e1.y, o1.y);
        w2[kp][6] = pack2(e1.z, o1.z); w2[kp][7] = pack2(e1.w, o1.w);
    }

    // lane's value id: v = lane>>1 = b*8 + jj*4 + g
    int v_me = lane >> 1;
    int b_me = v_me >> 3;
    int o_me = v_me & 7;
    int jj_me = o_me >> 2, g_me = o_me & 3;
    int jg_me = jg0 + jj_me;
    int bg_me = clu * 2 + b_me;
    bool owner = ((lane & 7) == 0);

    // init h0 into buf 0 (local copy: 2 batches x 256 j)
    {
        int b = tid >> 8, j = tid & 255;
        h_s[0][b * Hsz + j] = h0[(clu * 2 + b) * Hsz + j];
    }
    float c_val = owner ? c0[bg_me * Hsz + jg_me] : 0.f;
    float xv = g_xp[(size_t)bg_me * Msz + jg_me * 4 + g_me];   // t=0

    float* out_hj = out + (size_t)bg_me * Ssz * Hsz + jg_me;
    const float* xp_bj = g_xp + (size_t)bg_me * Msz + jg_me * 4 + g_me;
    const size_t fin_off = (size_t)Bsz * Ssz * Hsz;

    __syncthreads();
    asm volatile("barrier.cluster.arrive.aligned;" ::: "memory");
    asm volatile("barrier.cluster.wait.aligned;" ::: "memory");

    for (int t = 0; t < Ssz; t++) {
        int cur = t & 1, nb = cur ^ 1;
        unsigned par = ((unsigned)(t - 1) >> 1) & 1u;
        bool not_last = (t + 1 < Ssz);

        if (t) mbar_wait(my_mb + cur * 8, par);     // full[cur]: data landed

        const float* hb = &h_s[cur][0];

        // batch 0 pass
        ulonglong2 hA0 = *(const ulonglong2*)(hb + 8 * lane);
        ulonglong2 hB0 = *(const ulonglong2*)(hb + 8 * lane + 4);
        ull h20[4] = {hA0.x, hA0.y, hB0.x, hB0.y};
        ull acc2[8];
        #pragma unroll
        for (int o = 0; o < 8; o++) acc2[o] = 0ull;
        #pragma unroll
        for (int kp = 0; kp < 4; kp++)
            #pragma unroll
            for (int o = 0; o < 8; o++) fma2(acc2[o], w2[kp][o], h20[kp]);

        float acc[16];
        #pragma unroll
        for (int o = 0; o < 8; o++) {
            float lo, hi; unpack2(lo, hi, acc2[o]); acc[o] = lo + hi;
        }

        // batch 1 pass
        ulonglong2 hA1 = *(const ulonglong2*)(hb + Hsz + 8 * lane);
        ulonglong2 hB1 = *(const ulonglong2*)(hb + Hsz + 8 * lane + 4);
        ull h21[4] = {hA1.x, hA1.y, hB1.x, hB1.y};
        #pragma unroll
        for (int o = 0; o < 8; o++) acc2[o] = 0ull;
        #pragma unroll
        for (int kp = 0; kp < 4; kp++)
            #pragma unroll
            for (int o = 0; o < 8; o++) fma2(acc2[o], w2[kp][o], h21[kp]);
        #pragma unroll
        for (int o = 0; o < 8; o++) {
            float lo, hi; unpack2(lo, hi, acc2[o]); acc[8 + o] = lo + hi;
        }

        __syncthreads();   // all warps done reading buf[cur]

        if (not_last && tid == 0) {
            mbar_expect_tx(my_mb + cur * 8, 2048);  // re-arm full[cur] for t+2
            #pragma unroll
            for (int r = 0; r < 8; r++)             // tell peers buf[cur] is free
                asm volatile("mbarrier.arrive.shared::cluster.b64 _, [%0];"
                             :: "r"(s_rmb[r] + 16u + (unsigned)cur * 8u) : "memory");
        }

        // butterfly: 16 values over 32 lanes; lane L ends with value (L>>1)
        int cnt = 16;
        #pragma unroll
        for (int off = 16; off >= 2; off >>= 1) {
            cnt >>= 1;
            bool upper = (lane & off) != 0;
            #pragma unroll
            for (int v = 0; v < cnt; v++) {
                float send = upper ? acc[v] : acc[v + cnt];
                float recv = __shfl_xor_sync(0xffffffffu, send, off);
                acc[v] = (upper ? acc[v + cnt] : acc[v]) + recv;
            }
        }
        acc[0] += __shfl_xor_sync(0xffffffffu, acc[0], 1);

        float pre = acc[0] + xv;
        float a;
        if (g_me == 2) { float e = __expf(-2.f * pre); a = __fdividef(2.f, 1.f + e) - 1.f; }
        else           { a = __fdividef(1.f, 1.f + __expf(-pre)); }

        int base = lane & ~7;
        float fg = __shfl_sync(0xffffffffu, a, base);
        float ig = __shfl_sync(0xffffffffu, a, base + 2);
        float cg = __shfl_sync(0xffffffffu, a, base + 4);
        float og = __shfl_sync(0xffffffffu, a, base + 6);

        float hn = 0.f;
        if (owner) {
            c_val = c_val * fg + ig * cg;
            float e = __expf(-2.f * c_val);
            hn = og * (__fdividef(2.f, 1.f + e) - 1.f);
            out_hj[(size_t)t * Hsz] = hn;
            if (!not_last && write_finals) {
                out[fin_off + (size_t)bg_me * Hsz + jg_me] = hn;                          // h_f
                out[fin_off + (size_t)Bsz * Hsz + (size_t)bg_me * Hsz + jg_me] = c_val;   // c_f
            }
        }

        if (not_last) {
            xv = __ldg(xp_bj + (size_t)(t + 1) * Bsz * Msz);   // overlaps empty wait
            if (t) mbar_wait(my_mb + 16 + nb * 8, par);        // peers done reading buf[nb]
            if (owner) {
                unsigned off4 = (unsigned)(nb * (2 * Hsz) + b_me * Hsz + jg_me) * 4u;
                unsigned hbits = __float_as_uint(hn);
                #pragma unroll
                for (int r = 0; r < 8; r++)
                    asm volatile(
                        "st.async.weak.shared::cluster.mbarrier::complete_tx::bytes.b32 [%0], %1, [%2];"
                        :: "r"(s_rh[r] + off4), "r"(hbits),
                           "r"(s_rmb[r] + (unsigned)nb * 8u) : "memory");
            }
        }
    }

    // lifetime safety: no CTA exits while cluster peers may have ops in flight
    asm volatile("barrier.cluster.arrive.aligned;" ::: "memory");
    asm volatile("barrier.cluster.wait.aligned;" ::: "memory");
}

// ------------------------------- launch ----------------------------------------
extern "C" void kernel_launch(void* const* d_in, const int* in_sizes, int n_in,
                              void* d_out, int out_size) {
    const float* x  = (const float*)d_in[0];
    const float* h0 = (const float*)d_in[1];
    const float* c0 = (const float*)d_in[2];
    const float* Wf = (const float*)d_in[3];
    const float* bf = (const float*)d_in[4];
    const float* Wi = (const float*)d_in[5];
    const float* bi = (const float*)d_in[6];
    const float* Wc = (const float*)d_in[7];
    const float* bc = (const float*)d_in[8];
    const float* Wo = (const float*)d_in[9];
    const float* bo = (const float*)d_in[10];
    float* out = (float*)d_out;

    int full = Bsz * Ssz * Hsz + 2 * Bsz * Hsz;
    int write_finals = (out_size >= full) ? 1 : 0;

    pack_kernel<<<512, 256>>>(Wf, Wi, Wc, Wo, bf, bi, bc, bo);

    dim3 grid_x(8, 512);
    xproj_kernel<<<grid_x, 256>>>(x);

    lstm_rec<<<128, 512>>>(h0, c0, out, write_finals);
}